// round 4
// baseline (speedup 1.0000x reference)
#include <cuda_runtime.h>

// CentDif: 6th-order central difference + 2-channel advection combine.
// u: [16384, 2, 2048] fp32. Pipelined: 8 rows per CTA, double-buffered smem
// filled via cp.async.cg so loads for row r+1 overlap compute/store of row r.

#define M_DIM 16384
#define L_DIM 2048
#define IGST  10
#define NTHREADS 256           // 256 * 8 outputs = 2048 = L_DIM
#define ROWS   8               // m-rows per CTA
#define LP     (L_DIM + 16)    // padded channel row (+4 front, +12 back)

__device__ __forceinline__ void cp_async16(float* smem_dst, const float* gmem_src) {
    unsigned s = (unsigned)__cvta_generic_to_shared(smem_dst);
    asm volatile("cp.async.cg.shared.global [%0], [%1], 16;\n" :: "r"(s), "l"(gmem_src));
}
__device__ __forceinline__ void cp_commit() {
    asm volatile("cp.async.commit_group;\n");
}
template <int N>
__device__ __forceinline__ void cp_wait() {
    asm volatile("cp.async.wait_group %0;\n" :: "n"(N));
}

__global__ __launch_bounds__(NTHREADS) void centdif_kernel(
    const float* __restrict__ u, float* __restrict__ out)
{
    __shared__ __align__(16) float sbuf[2][2][LP];

    const int m0  = blockIdx.x * ROWS;
    const int tid = threadIdx.x;
    const float c = (float)(1.0 / (60.0 * 0.012));  // 1/(60*DX)

    // ---- stage loader: 2 channels x 512 float4 / 256 thr = 4 cp.async/thread ----
    auto issue_stage = [&](int r, int buf) {
        const size_t base = (size_t)(m0 + r) * (2 * L_DIM);
        #pragma unroll
        for (int ch = 0; ch < 2; ++ch) {
            const float* src = u + base + (size_t)ch * L_DIM;
            float* dst = &sbuf[buf][ch][4];
            #pragma unroll
            for (int j = tid * 4; j < L_DIM; j += NTHREADS * 4)
                cp_async16(dst + j, src + j);
        }
        cp_commit();
    };

    issue_stage(0, 0);

    const int l0 = tid * 8;

    #pragma unroll 1
    for (int r = 0; r < ROWS; ++r) {
        const int buf = r & 1;
        if (r + 1 < ROWS) {
            issue_stage(r + 1, buf ^ 1);
            cp_wait<1>();          // stage r complete; stage r+1 in flight
        } else {
            cp_wait<0>();
        }
        __syncthreads();

        // ---- compute row r from sbuf[buf] (R3 vectorized form) ----
        const float* s0 = sbuf[buf][0];
        const float* s1 = sbuf[buf][1];

        float a[16], b[16];
        const float4* p0 = (const float4*)(s0 + l0);   // abs idx l0 -> u[l0-4]
        const float4* p1 = (const float4*)(s1 + l0);
        #pragma unroll
        for (int q = 0; q < 4; ++q) {
            float4 v0 = p0[q];
            a[4*q+0] = v0.x; a[4*q+1] = v0.y; a[4*q+2] = v0.z; a[4*q+3] = v0.w;
            float4 v1 = p1[q];
            b[4*q+0] = v1.x; b[4*q+1] = v1.y; b[4*q+2] = v1.z; b[4*q+3] = v1.w;
        }

        float r0[8], r1[8];
        #pragma unroll
        for (int i = 0; i < 8; ++i) {
            const int l = l0 + i;
            float du0 = 0.0f, du1 = 0.0f;
            if (l >= IGST && l < L_DIM - IGST) {
                du0 = (-a[i+1] + 9.0f*a[i+2] - 45.0f*a[i+3]
                       + 45.0f*a[i+5] - 9.0f*a[i+6] + a[i+7]) * c;
                du1 = (-b[i+1] + 9.0f*b[i+2] - 45.0f*b[i+3]
                       + 45.0f*b[i+5] - 9.0f*b[i+6] + b[i+7]) * c;
            }
            const float uu0 = a[i+4];
            const float uu1 = b[i+4];
            r0[i] = -(uu1 * du0 + uu0 * du1);
            r1[i] = -(2.0f * du0 + uu1 * du1);
        }

        const size_t base = (size_t)(m0 + r) * (2 * L_DIM);
        float4* o0 = (float4*)(out + base + l0);
        float4* o1 = (float4*)(out + base + L_DIM + l0);
        o0[0] = make_float4(r0[0], r0[1], r0[2], r0[3]);
        o0[1] = make_float4(r0[4], r0[5], r0[6], r0[7]);
        o1[0] = make_float4(r1[0], r1[1], r1[2], r1[3]);
        o1[1] = make_float4(r1[4], r1[5], r1[6], r1[7]);

        __syncthreads();   // buffer buf is consumed; safe to refill next iter
    }
}

extern "C" void kernel_launch(void* const* d_in, const int* in_sizes, int n_in,
                              void* d_out, int out_size)
{
    const float* u = (const float*)d_in[0];
    float* out = (float*)d_out;
    centdif_kernel<<<M_DIM / ROWS, NTHREADS>>>(u, out);
}

// round 5
// speedup vs baseline: 1.1751x; 1.1751x over previous
#include <cuda_runtime.h>

// CentDif: 6th-order central difference + 2-channel advection combine.
// u: [16384, 2, 2048] fp32. No smem: each thread computes 8 consecutive
// outputs from a 16-float register window per channel (4x LDG.128), relying
// on L1 to absorb the inter-thread halo overlap. No barriers, pure
// LDG -> FFMA -> STG streaming.

#define M_DIM 16384
#define L_DIM 2048
#define IGST  10
#define NTHREADS 256   // 256 * 8 = 2048 = L_DIM

__global__ __launch_bounds__(NTHREADS) void centdif_kernel(
    const float* __restrict__ u, float* __restrict__ out)
{
    const int m = blockIdx.x;
    const size_t base = (size_t)m * (2 * L_DIM);
    const int l0 = threadIdx.x * 8;

    float4* o0 = (float4*)(out + base + l0);
    float4* o1 = (float4*)(out + base + L_DIM + l0);

    // Threads whose whole 8-output span is ghost region: outputs are exactly 0
    // (du == 0 there). Also avoids OOB window loads at l0==0 / l0==2040.
    if (l0 + 7 < IGST || l0 >= L_DIM - IGST) {
        const float4 z = make_float4(0.f, 0.f, 0.f, 0.f);
        o0[0] = z; o0[1] = z;
        o1[0] = z; o1[1] = z;
        return;
    }

    const float c = (float)(1.0 / (60.0 * 0.012));  // 1/(60*DX)

    // Register window: a[k] = u0[l0 - 4 + k], b[k] = u1[l0 - 4 + k], k=0..15.
    // l0-4 is a multiple of 4 -> 16B-aligned float4 loads. Front-batched for MLP.
    const float4* p0 = (const float4*)(u + base + l0 - 4);
    const float4* p1 = (const float4*)(u + base + L_DIM + l0 - 4);

    float4 va[4], vb[4];
    #pragma unroll
    for (int q = 0; q < 4; ++q) va[q] = __ldg(p0 + q);
    #pragma unroll
    for (int q = 0; q < 4; ++q) vb[q] = __ldg(p1 + q);

    float a[16], b[16];
    #pragma unroll
    for (int q = 0; q < 4; ++q) {
        a[4*q+0] = va[q].x; a[4*q+1] = va[q].y; a[4*q+2] = va[q].z; a[4*q+3] = va[q].w;
        b[4*q+0] = vb[q].x; b[4*q+1] = vb[q].y; b[4*q+2] = vb[q].z; b[4*q+3] = vb[q].w;
    }

    float r0[8], r1[8];
    #pragma unroll
    for (int i = 0; i < 8; ++i) {
        const int l = l0 + i;
        float du0 = 0.0f, du1 = 0.0f;
        if (l >= IGST && l < L_DIM - IGST) {
            // taps: l-3 -> a[i+1], l-2 -> a[i+2], l-1 -> a[i+3],
            //       l+1 -> a[i+5], l+2 -> a[i+6], l+3 -> a[i+7]
            du0 = (-a[i+1] + 9.0f*a[i+2] - 45.0f*a[i+3]
                   + 45.0f*a[i+5] - 9.0f*a[i+6] + a[i+7]) * c;
            du1 = (-b[i+1] + 9.0f*b[i+2] - 45.0f*b[i+3]
                   + 45.0f*b[i+5] - 9.0f*b[i+6] + b[i+7]) * c;
        }
        const float uu0 = a[i+4];   // u0[l]
        const float uu1 = b[i+4];   // u1[l]
        r0[i] = -(uu1 * du0 + uu0 * du1);
        r1[i] = -(2.0f * du0 + uu1 * du1);
    }

    o0[0] = make_float4(r0[0], r0[1], r0[2], r0[3]);
    o0[1] = make_float4(r0[4], r0[5], r0[6], r0[7]);
    o1[0] = make_float4(r1[0], r1[1], r1[2], r1[3]);
    o1[1] = make_float4(r1[4], r1[5], r1[6], r1[7]);
}

extern "C" void kernel_launch(void* const* d_in, const int* in_sizes, int n_in,
                              void* d_out, int out_size)
{
    const float* u = (const float*)d_in[0];
    float* out = (float*)d_out;
    centdif_kernel<<<M_DIM, NTHREADS>>>(u, out);
}

// round 6
// speedup vs baseline: 1.1797x; 1.0039x over previous
#include <cuda_runtime.h>

// CentDif: 6th-order central difference + 2-channel advection combine.
// u: [16384, 2, 2048] fp32. No smem, no barriers: each thread computes 8
// consecutive outputs from a 16-float register window per channel
// (4x LDG.128), L1 absorbs inter-thread halo overlap. 128-thread CTAs
// (half-row each) for finer scheduling granularity; streaming stores.

#define M_DIM 16384
#define L_DIM 2048
#define IGST  10
#define NTHREADS 128   // half-row: 128 * 8 = 1024 floats

__global__ __launch_bounds__(NTHREADS) void centdif_kernel(
    const float* __restrict__ u, float* __restrict__ out)
{
    const int bid  = blockIdx.x;
    const int m    = bid >> 1;
    const int half = bid & 1;
    const size_t base = (size_t)m * (2 * L_DIM);
    const int l0 = (half * (L_DIM / 2)) + threadIdx.x * 8;

    float4* o0 = (float4*)(out + base + l0);
    float4* o1 = (float4*)(out + base + L_DIM + l0);

    // Fully-ghost spans: outputs exactly 0; also avoids OOB window loads.
    if (l0 + 7 < IGST || l0 >= L_DIM - IGST) {
        const float4 z = make_float4(0.f, 0.f, 0.f, 0.f);
        __stcs(o0 + 0, z); __stcs(o0 + 1, z);
        __stcs(o1 + 0, z); __stcs(o1 + 1, z);
        return;
    }

    const float c = (float)(1.0 / (60.0 * 0.012));  // 1/(60*DX)

    // Register window: a[k] = u0[l0-4+k], b[k] = u1[l0-4+k], k=0..15.
    // l0-4 is a multiple of 4 -> aligned float4 loads; front-batched for MLP.
    const float4* p0 = (const float4*)(u + base + l0 - 4);
    const float4* p1 = (const float4*)(u + base + L_DIM + l0 - 4);

    float4 va[4], vb[4];
    #pragma unroll
    for (int q = 0; q < 4; ++q) va[q] = __ldg(p0 + q);
    #pragma unroll
    for (int q = 0; q < 4; ++q) vb[q] = __ldg(p1 + q);

    float a[16], b[16];
    #pragma unroll
    for (int q = 0; q < 4; ++q) {
        a[4*q+0] = va[q].x; a[4*q+1] = va[q].y; a[4*q+2] = va[q].z; a[4*q+3] = va[q].w;
        b[4*q+0] = vb[q].x; b[4*q+1] = vb[q].y; b[4*q+2] = vb[q].z; b[4*q+3] = vb[q].w;
    }

    float r0[8], r1[8];
    #pragma unroll
    for (int i = 0; i < 8; ++i) {
        const int l = l0 + i;
        float du0 = 0.0f, du1 = 0.0f;
        if (l >= IGST && l < L_DIM - IGST) {
            // taps: l-3 -> a[i+1], l-2 -> a[i+2], l-1 -> a[i+3],
            //       l+1 -> a[i+5], l+2 -> a[i+6], l+3 -> a[i+7]
            du0 = (-a[i+1] + 9.0f*a[i+2] - 45.0f*a[i+3]
                   + 45.0f*a[i+5] - 9.0f*a[i+6] + a[i+7]) * c;
            du1 = (-b[i+1] + 9.0f*b[i+2] - 45.0f*b[i+3]
                   + 45.0f*b[i+5] - 9.0f*b[i+6] + b[i+7]) * c;
        }
        const float uu0 = a[i+4];   // u0[l]
        const float uu1 = b[i+4];   // u1[l]
        r0[i] = -(uu1 * du0 + uu0 * du1);
        r1[i] = -(2.0f * du0 + uu1 * du1);
    }

    __stcs(o0 + 0, make_float4(r0[0], r0[1], r0[2], r0[3]));
    __stcs(o0 + 1, make_float4(r0[4], r0[5], r0[6], r0[7]));
    __stcs(o1 + 0, make_float4(r1[0], r1[1], r1[2], r1[3]));
    __stcs(o1 + 1, make_float4(r1[4], r1[5], r1[6], r1[7]));
}

extern "C" void kernel_launch(void* const* d_in, const int* in_sizes, int n_in,
                              void* d_out, int out_size)
{
    const float* u = (const float*)d_in[0];
    float* out = (float*)d_out;
    centdif_kernel<<<M_DIM * 2, NTHREADS>>>(u, out);
}